// round 12
// baseline (speedup 1.0000x reference)
#include <cuda_runtime.h>
#include <cuda_bf16.h>

// S4D kernel: K[h,l] = 2*Re( sum_n Ct[h,n] * exp(dtA[h,n]*l) )
// R12 change: amortize chunk starts over 2x longer chunks. 128 threads per
// head, 32 l-values per thread (was 256x16): start cost per output halves
// (-15% packed work, -50% MUFU). Two heads per 256-thread block keep
// occupancy; kGrp=4 chains + acc[32] fit the 128-reg budget of
// __launch_bounds__(256,2). Lagged-W recurrence (4-cyc carried chain) kept.

static constexpr int kH     = 1024;
static constexpr int kN2    = 32;
static constexpr int kL     = 4096;
static constexpr int kChunk = 32;
static constexpr int kTPH   = 128;           // threads per head; kTPH*kChunk == kL
static constexpr int kTPB   = 256;           // 2 heads per block
static constexpr int kPairs = kN2 / 2;
static constexpr int kGrp   = 4;             // pairs per ILP group

typedef unsigned long long u64;

__device__ __forceinline__ u64 pk2(float lo, float hi) {
    u64 r; asm("mov.b64 %0, {%1, %2};" : "=l"(r) : "f"(lo), "f"(hi)); return r;
}
__device__ __forceinline__ void upk2(u64 v, float& lo, float& hi) {
    asm("mov.b64 {%0, %1}, %2;" : "=f"(lo), "=f"(hi) : "l"(v));
}
__device__ __forceinline__ u64 fma2(u64 a, u64 b, u64 c) {
    u64 r; asm("fma.rn.f32x2 %0, %1, %2, %3;" : "=l"(r) : "l"(a), "l"(b), "l"(c)); return r;
}
__device__ __forceinline__ u64 mul2(u64 a, u64 b) {
    u64 r; asm("mul.rn.f32x2 %0, %1, %2;" : "=l"(r) : "l"(a), "l"(b)); return r;
}
__device__ __forceinline__ u64 add2(u64 a, u64 b) {
    u64 r; asm("add.rn.f32x2 %0, %1, %2;" : "=l"(r) : "l"(a), "l"(b)); return r;
}
__device__ __forceinline__ float ex2a(float x) {
    float r; asm("ex2.approx.f32 %0, %1;" : "=f"(r) : "f"(x)); return r;
}
__device__ __forceinline__ float sina(float x) {
    float r; asm("sin.approx.f32 %0, %1;" : "=f"(r) : "f"(x)); return r;
}
__device__ __forceinline__ float cosa(float x) {
    float r; asm("cos.approx.f32 %0, %1;" : "=f"(r) : "f"(x)); return r;
}

static __device__ __forceinline__ u64 SGN2() { return 0x8000000080000000ULL; }

// Packed chunk start for a mode pair: u0 = Re(Ct z^{l0}), u1 = Re(Ct z^{l0+1}).
__device__ __forceinline__ void pair_start(
    float4 g1, float4 g2, float4 g3,
    u64 l0f2, u64 nINV2PI2, u64 MAGIC2, u64 nMAGIC2, u64 PI2HI2, u64 PI2MID2,
    u64& u0pk, u64& u1pk)
{
    u64 dreL2 = pk2(g1.x, g1.y);          // dre * log2(e), per mode
    u64 dim2  = pk2(g1.z, g1.w);
    u64 m2 = mul2(dreL2, l0f2);
    float m0, m1; upk2(m2, m0, m1);
    float mag0 = ex2a(m0), mag1 = ex2a(m1);

    u64 p2   = mul2(dim2, l0f2);
    u64 e2   = fma2(dim2, l0f2, p2 ^ SGN2());     // exact residual of dim*l0
    u64 nk2  = fma2(p2, nINV2PI2, MAGIC2);        // MAGIC - p/2pi (rounded on int grid)
    u64 nkf2 = add2(nk2, nMAGIC2);                // = -rint(p/2pi)
    u64 r2   = fma2(nkf2, PI2HI2, p2);
    r2       = add2(r2, fma2(nkf2, PI2MID2, e2));
    float r0, r1; upk2(r2, r0, r1);
    float s0 = sina(r0), c0 = cosa(r0);
    float s1 = sina(r1), c1 = cosa(r1);

    u64 mag2 = pk2(mag0, mag1);
    u64 pr2  = mul2(mag2, pk2(c0, c1));
    u64 pi2  = mul2(mag2, pk2(s0, s1));
    u64 ctr2 = pk2(g2.x, g2.y);
    u64 cti2 = pk2(g2.z, g2.w);
    u64 qr2  = fma2(cti2, pi2 ^ SGN2(), mul2(ctr2, pr2));   // ctr*pr - cti*pi
    u64 qi2  = fma2(cti2, pr2,          mul2(ctr2, pi2));   // ctr*pi + cti*pr
    u64 wr2  = pk2(g3.x, g3.y);
    u64 nwi2 = pk2(g3.z, g3.w);
    u0pk = qr2;
    u1pk = fma2(qi2, nwi2, mul2(qr2, wr2));                  // Re(q*z)
}

struct ModeParams {
    float dreL2, dim, ctr, cti, wr, nwi, a, nb;
};

__device__ __forceinline__ ModeParams mode_setup(float dt, float lAr, float Aim,
                                                 float cr, float ci) {
    const float LOG2E = 1.44269504088896341f;
    ModeParams mp;
    float Are = -__expf(lAr);
    float dre = Are * dt;
    float dim = Aim * dt;
    float er  = __expf(dre);
    float sn, cs;
    __sincosf(dim, &sn, &cs);
    float wr = er * cs, wi = er * sn;
    float e1r = wr - 1.0f, e1i = wi;
    float nr = cr * e1r - ci * e1i;
    float ni = cr * e1i + ci * e1r;
    float a2   = Are * Are + Aim * Aim;
    float inva = 2.0f / a2;                  // factor 2 of output folded in
    mp.ctr   = (nr * Are + ni * Aim) * inva;
    mp.cti   = (ni * Are - nr * Aim) * inva;
    mp.dreL2 = dre * LOG2E;
    mp.dim   = dim;
    mp.wr    = wr;
    mp.nwi   = -wi;
    mp.a     = 2.0f * wr;
    mp.nb    = -(er * er);
    return mp;
}

__global__ __launch_bounds__(kTPB, 2) void s4d_kernel(
    const float* __restrict__ log_dt,
    const float* __restrict__ C_real,
    const float* __restrict__ C_imag,
    const float* __restrict__ log_A_real,
    const float* __restrict__ A_imag,
    float* __restrict__ out)
{
    __shared__ float4 s_g1[2][kPairs];   // {dreL2_0, dreL2_1, dim_0, dim_1}
    __shared__ float4 s_g2[2][kPairs];   // {ctr_0,  ctr_1,  cti_0, cti_1}
    __shared__ float4 s_g3[2][kPairs];   // {wr_0,   wr_1,   nwi_0, nwi_1}
    __shared__ float4 s_g4[2][kPairs];   // {a_0,    a_1,    nb_0,  nb_1}

    const int h_base = blockIdx.x * 2;
    const int tid    = threadIdx.x;

    if (tid < 2 * kPairs) {
        const int lh = tid >> 4;            // which head (0/1)
        const int p  = tid & (kPairs - 1);  // which pair
        const int h  = h_base + lh;
        const int n0 = 2 * p, n1 = n0 + 1;
        float dt = __expf(log_dt[h]);
        ModeParams m0 = mode_setup(dt, log_A_real[h * kN2 + n0], A_imag[h * kN2 + n0],
                                   C_real[h * kN2 + n0], C_imag[h * kN2 + n0]);
        ModeParams m1 = mode_setup(dt, log_A_real[h * kN2 + n1], A_imag[h * kN2 + n1],
                                   C_real[h * kN2 + n1], C_imag[h * kN2 + n1]);
        s_g1[lh][p] = make_float4(m0.dreL2, m1.dreL2, m0.dim, m1.dim);
        s_g2[lh][p] = make_float4(m0.ctr,   m1.ctr,   m0.cti, m1.cti);
        s_g3[lh][p] = make_float4(m0.wr,    m1.wr,    m0.nwi, m1.nwi);
        s_g4[lh][p] = make_float4(m0.a,     m1.a,     m0.nb,  m1.nb);
    }
    __syncthreads();

    const int lh = tid >> 7;              // head within block
    const int lt = tid & (kTPH - 1);      // thread within head
    const int h  = h_base + lh;

    const float l0f = (float)(lt * kChunk);
    const u64 l0f2 = pk2(l0f, l0f);

    const float INV2PI  = 0.15915494309189535f;
    const float PI2HI   = 6.28318548202514648f;   // fp32(2*pi)
    const float PI2MID  = -1.74845600e-7f;        // 2*pi - PI2HI
    const float MAGIC   = 12582912.0f;            // 1.5 * 2^23
    const u64 nINV2PI2 = pk2(-INV2PI, -INV2PI);
    const u64 MAGIC2   = pk2(MAGIC, MAGIC);
    const u64 nMAGIC2  = pk2(-MAGIC, -MAGIC);
    const u64 PI2HI2   = pk2(PI2HI, PI2HI);
    const u64 PI2MID2  = pk2(PI2MID, PI2MID);

    u64 acc[kChunk];
    #pragma unroll
    for (int j = 0; j < kChunk; j++) acc[j] = 0ULL;   // packed {0.0f, 0.0f}

    #pragma unroll 1
    for (int g = 0; g < kPairs / kGrp; g++) {
        u64 A[kGrp], NB[kGrp], U1[kGrp], W[kGrp];

        // Start kGrp independent chains (MUFU bursts overlap via ILP).
        #pragma unroll
        for (int i = 0; i < kGrp; i++) {
            const int p = g * kGrp + i;
            float4 g4 = s_g4[lh][p];
            A[i]  = pk2(g4.x, g4.y);
            NB[i] = pk2(g4.z, g4.w);
            u64 u0;
            pair_start(s_g1[lh][p], s_g2[lh][p], s_g3[lh][p],
                       l0f2, nINV2PI2, MAGIC2, nMAGIC2, PI2HI2, PI2MID2,
                       u0, U1[i]);
            acc[0] = add2(acc[0], u0);
            acc[1] = add2(acc[1], U1[i]);
            W[i]   = mul2(u0, NB[i]);      // W = (-b)*u_0, lagged product
        }

        // Recurrence: carried chain is ONE fma2 per link (4 cyc); the mul2
        // feeding W has a full link of slack; the acc add is off-chain.
        #pragma unroll
        for (int j = 2; j < kChunk; j++) {
            #pragma unroll
            for (int i = 0; i < kGrp; i++) {
                u64 un = fma2(U1[i], A[i], W[i]);   // u_j = a*u_{j-1} - b*u_{j-2}
                W[i]   = mul2(U1[i], NB[i]);        // (-b)*u_{j-1}, for next link
                acc[j] = add2(acc[j], un);
                U1[i]  = un;
            }
        }
    }

    // Reduce packed halves, store as float4 (128B per thread, aligned).
    float4* outv = (float4*)(out + (size_t)h * kL + (size_t)lt * kChunk);
    #pragma unroll
    for (int v = 0; v < kChunk / 4; v++) {
        float a0, a1, b0, b1, c0, c1, d0, d1;
        upk2(acc[4 * v + 0], a0, a1);
        upk2(acc[4 * v + 1], b0, b1);
        upk2(acc[4 * v + 2], c0, c1);
        upk2(acc[4 * v + 3], d0, d1);
        float4 o;
        o.x = a0 + a1;
        o.y = b0 + b1;
        o.z = c0 + c1;
        o.w = d0 + d1;
        outv[v] = o;
    }
}

extern "C" void kernel_launch(void* const* d_in, const int* in_sizes, int n_in,
                              void* d_out, int out_size) {
    const float* log_dt     = (const float*)d_in[0];
    const float* C_real     = (const float*)d_in[1];
    const float* C_imag     = (const float*)d_in[2];
    const float* log_A_real = (const float*)d_in[3];
    const float* A_imag     = (const float*)d_in[4];
    float* out = (float*)d_out;

    s4d_kernel<<<kH / 2, kTPB>>>(log_dt, C_real, C_imag, log_A_real, A_imag, out);
}

// round 16
// speedup vs baseline: 2.1375x; 2.1375x over previous
#include <cuda_runtime.h>
#include <cuda_bf16.h>
#include <cstdint>

// S4D via per-head GEMM on legacy tensor cores (mma.sync bf16 — available at
// the plain sm_103 PTX target, unlike tcgen05 which the harness toolchain
// rejects).
//   K[h, 32m+j] = sum_k A[m,k]*B[j,k],  m<128, j<32, k<64
//   A[m,2n] = Re(Ct_n z_n^{32m}), A[m,2n+1] = Im(...)   (seeds, in registers)
//   B[j,2n] = Re(z_n^j),          B[j,2n+1] = -Im(z_n^j) (smem table)
// Split-by-difference bf16: D = Ah*Bh + Ah*Bl + Al*Bh, f32 accumulators.
// m16n8k16 fragments are generated directly in registers (no ldmatrix).

typedef unsigned long long u64;
typedef unsigned int u32;

static constexpr int kH = 1024;
static constexpr int kN2 = 32;
static constexpr int kL = 4096;
static constexpr int kTPB = 128;
static constexpr int TABS = 36;   // smem table stride (words): 4g+t banks, conflict-free

// ---- packed f32x2 helpers ----
__device__ __forceinline__ u64 pk2(float lo, float hi) {
    u64 r; asm("mov.b64 %0, {%1, %2};" : "=l"(r) : "f"(lo), "f"(hi)); return r;
}
__device__ __forceinline__ void upk2(u64 v, float& lo, float& hi) {
    asm("mov.b64 {%0, %1}, %2;" : "=f"(lo), "=f"(hi) : "l"(v));
}
__device__ __forceinline__ u64 fma2(u64 a, u64 b, u64 c) {
    u64 r; asm("fma.rn.f32x2 %0, %1, %2, %3;" : "=l"(r) : "l"(a), "l"(b), "l"(c)); return r;
}
__device__ __forceinline__ u64 mul2(u64 a, u64 b) {
    u64 r; asm("mul.rn.f32x2 %0, %1, %2;" : "=l"(r) : "l"(a), "l"(b)); return r;
}
__device__ __forceinline__ u64 add2(u64 a, u64 b) {
    u64 r; asm("add.rn.f32x2 %0, %1, %2;" : "=l"(r) : "l"(a), "l"(b)); return r;
}
__device__ __forceinline__ float ex2a(float x) {
    float r; asm("ex2.approx.f32 %0, %1;" : "=f"(r) : "f"(x)); return r;
}
__device__ __forceinline__ float sina(float x) {
    float r; asm("sin.approx.f32 %0, %1;" : "=f"(r) : "f"(x)); return r;
}
__device__ __forceinline__ float cosa(float x) {
    float r; asm("cos.approx.f32 %0, %1;" : "=f"(r) : "f"(x)); return r;
}
static __device__ __forceinline__ u64 SGN2() { return 0x8000000080000000ULL; }

// bf16x2 pack: low half = a, high half = b
__device__ __forceinline__ u32 pk_bf(float a, float b) {
    u32 r; asm("cvt.rn.satfinite.bf16x2.f32 %0, %1, %2;" : "=r"(r) : "f"(b), "f"(a));
    return r;
}
// split (x, y) into bf16x2 hi word + bf16x2 residual word
__device__ __forceinline__ void split_pair(float x, float y, u32& hi, u32& lo) {
    u32 hb = pk_bf(x, y);
    float xh = __uint_as_float(hb << 16);
    float yh = __uint_as_float(hb & 0xFFFF0000u);
    lo = pk_bf(x - xh, y - yh);
    hi = hb;
}

// D(16x8,f32) += A(16x16,bf16 row) * B(16x8,bf16 col); fragments per PTX ISA.
__device__ __forceinline__ void mma_bf16(float& d0, float& d1, float& d2, float& d3,
                                         u32 a0, u32 a1, u32 a2, u32 a3,
                                         u32 b0, u32 b1) {
    asm volatile(
        "mma.sync.aligned.m16n8k16.row.col.f32.bf16.bf16.f32 "
        "{%0,%1,%2,%3}, {%4,%5,%6,%7}, {%8,%9}, {%0,%1,%2,%3};"
        : "+f"(d0), "+f"(d1), "+f"(d2), "+f"(d3)
        : "r"(a0), "r"(a1), "r"(a2), "r"(a3), "r"(b0), "r"(b1));
}

// Packed mag/phase: pr = mag*cos, pi = mag*sin for two modes at l0.
__device__ __forceinline__ void zpow2(
    u64 dreL2, u64 dim2, u64 l0f2,
    u64 nINV2PI2, u64 MAGIC2, u64 nMAGIC2, u64 PI2HI2, u64 PI2MID2,
    u64& pr2o, u64& pi2o)
{
    u64 m2 = mul2(dreL2, l0f2);
    float m0, m1; upk2(m2, m0, m1);
    float mag0 = ex2a(m0), mag1 = ex2a(m1);

    u64 p2   = mul2(dim2, l0f2);
    u64 e2   = fma2(dim2, l0f2, p2 ^ SGN2());     // exact residual of dim*l0
    u64 nk2  = fma2(p2, nINV2PI2, MAGIC2);
    u64 nkf2 = add2(nk2, nMAGIC2);                // -rint(p/2pi)
    u64 r2   = fma2(nkf2, PI2HI2, p2);
    r2       = add2(r2, fma2(nkf2, PI2MID2, e2));
    float r0, r1; upk2(r2, r0, r1);
    float s0 = sina(r0), c0 = cosa(r0);
    float s1 = sina(r1), c1 = cosa(r1);
    u64 mag2 = pk2(mag0, mag1);
    pr2o = mul2(mag2, pk2(c0, c1));
    pi2o = mul2(mag2, pk2(s0, s1));
}

__global__ __launch_bounds__(kTPB, 4) void s4d_kernel(
    const float* __restrict__ log_dt,
    const float* __restrict__ C_real,
    const float* __restrict__ C_imag,
    const float* __restrict__ log_A_real,
    const float* __restrict__ A_imag,
    float* __restrict__ out)
{
    __shared__ float Pdre[kN2], Pdim[kN2], Pctr[kN2], Pcti[kN2];
    __shared__ u32 tabh[32 * TABS], tabl[32 * TABS];

    const int h   = blockIdx.x;
    const int tid = threadIdx.x;
    const int wid = tid >> 5;
    const int lid = tid & 31;
    const int g   = lid >> 2;     // fragment group (0..7)
    const int t   = lid & 3;      // thread-in-group (0..3)

    // ---- mode params ----
    if (tid < kN2) {
        const int n = tid;
        const float LOG2E = 1.44269504088896341f;
        float dt  = __expf(log_dt[h]);
        float Are = -__expf(log_A_real[h * kN2 + n]);
        float Aim = A_imag[h * kN2 + n];
        float dre = Are * dt;
        float dim = Aim * dt;
        float er  = __expf(dre);
        float sn, cs;
        __sincosf(dim, &sn, &cs);
        float wr = er * cs, wi = er * sn;
        float e1r = wr - 1.0f, e1i = wi;
        float cr = C_real[h * kN2 + n], ci = C_imag[h * kN2 + n];
        float nr = cr * e1r - ci * e1i;
        float ni = cr * e1i + ci * e1r;
        float a2   = Are * Are + Aim * Aim;
        float inva = 2.0f / a2;                  // output factor 2 folded in
        Pdre[n] = dre * LOG2E;
        Pdim[n] = dim;
        Pctr[n] = (nr * Are + ni * Aim) * inva;
        Pcti[n] = (ni * Are - nr * Aim) * inva;
    }
    __syncthreads();

    const float INV2PI  = 0.15915494309189535f;
    const float PI2HI   = 6.28318548202514648f;   // fp32(2*pi)
    const float PI2MID  = -1.74845600e-7f;        // 2*pi - PI2HI
    const float MAGIC   = 12582912.0f;            // 1.5 * 2^23
    const u64 nINV2PI2 = pk2(-INV2PI, -INV2PI);
    const u64 MAGIC2   = pk2(MAGIC, MAGIC);
    const u64 nMAGIC2  = pk2(-MAGIC, -MAGIC);
    const u64 PI2HI2   = pk2(PI2HI, PI2HI);
    const u64 PI2MID2  = pk2(PI2MID, PI2MID);

    // ---- B table: tab[j][n] = bf16x2{Re z_n^j, -Im z_n^j} (+ residual) ----
    {
        const int j  = tid & 31;
        const int ng = tid >> 5;                  // 4 mode-groups of 8
        const float jf = (float)j;
        const u64 jf2 = pk2(jf, jf);
        #pragma unroll
        for (int v = 0; v < 4; v++) {
            const int n0 = 8 * ng + 2 * v, n1 = n0 + 1;
            u64 dre2 = pk2(Pdre[n0], Pdre[n1]);
            u64 dim2 = pk2(Pdim[n0], Pdim[n1]);
            u64 pr2, pi2;
            zpow2(dre2, dim2, jf2, nINV2PI2, MAGIC2, nMAGIC2, PI2HI2, PI2MID2,
                  pr2, pi2);
            float r0, r1, i0, i1;
            upk2(pr2, r0, r1);
            upk2(pi2, i0, i1);
            u32 hi, lo;
            split_pair(r0, -i0, hi, lo);
            tabh[j * TABS + n0] = hi; tabl[j * TABS + n0] = lo;
            split_pair(r1, -i1, hi, lo);
            tabh[j * TABS + n1] = hi; tabl[j * TABS + n1] = lo;
        }
    }

    // ---- A fragments in registers: rows {g,g+8}+{0,16} of this warp's 32 ----
    u32 ah[2][4][4], al[2][4][4];   // [mtile][kstep][reg]
    #pragma unroll
    for (int mt = 0; mt < 2; mt++) {
        const int rbase = 32 * wid + 16 * mt;
        #pragma unroll
        for (int ks = 0; ks < 4; ks++) {
            const int n0 = 8 * ks + t, n1 = n0 + 4;
            u64 dre2 = pk2(Pdre[n0], Pdre[n1]);
            u64 dim2 = pk2(Pdim[n0], Pdim[n1]);
            u64 ctr2 = pk2(Pctr[n0], Pctr[n1]);
            u64 cti2 = pk2(Pcti[n0], Pcti[n1]);
            #pragma unroll
            for (int rh = 0; rh < 2; rh++) {      // rows g and g+8 -> regs {0,2} / {1,3}
                const float l0f = (float)(32 * (rbase + g + 8 * rh));
                const u64 l0f2 = pk2(l0f, l0f);
                u64 pr2, pi2;
                zpow2(dre2, dim2, l0f2, nINV2PI2, MAGIC2, nMAGIC2, PI2HI2, PI2MID2,
                      pr2, pi2);
                // q = Ct * (pr + i pi)
                u64 qr2 = fma2(cti2, pi2 ^ SGN2(), mul2(ctr2, pr2));
                u64 qi2 = fma2(cti2, pr2,          mul2(ctr2, pi2));
                float qr0, qr1, qi0, qi1;
                upk2(qr2, qr0, qr1);
                upk2(qi2, qi0, qi1);
                split_pair(qr0, qi0, ah[mt][ks][0 + rh], al[mt][ks][0 + rh]);
                split_pair(qr1, qi1, ah[mt][ks][2 + rh], al[mt][ks][2 + rh]);
            }
        }
    }
    __syncthreads();

    // ---- main GEMM: for each n-tile, 24 mma (4 ksteps x 2 mtiles x 3 products) ----
    #pragma unroll
    for (int jt = 0; jt < 4; jt++) {
        const int jr = (8 * jt + g) * TABS;
        u32 bh[8], bl[8];
        #pragma unroll
        for (int ks = 0; ks < 4; ks++) {
            bh[2 * ks]     = tabh[jr + 8 * ks + t];
            bh[2 * ks + 1] = tabh[jr + 8 * ks + t + 4];
            bl[2 * ks]     = tabl[jr + 8 * ks + t];
            bl[2 * ks + 1] = tabl[jr + 8 * ks + t + 4];
        }
        float dA[2][4] = {{0,0,0,0},{0,0,0,0}};   // ks even chain
        float dB[2][4] = {{0,0,0,0},{0,0,0,0}};   // ks odd chain
        #pragma unroll
        for (int ks = 0; ks < 4; ks++) {
            #pragma unroll
            for (int mt = 0; mt < 2; mt++) {
                float* d = (ks & 1) ? dB[mt] : dA[mt];
                mma_bf16(d[0], d[1], d[2], d[3],
                         ah[mt][ks][0], ah[mt][ks][1], ah[mt][ks][2], ah[mt][ks][3],
                         bh[2 * ks], bh[2 * ks + 1]);
                mma_bf16(d[0], d[1], d[2], d[3],
                         ah[mt][ks][0], ah[mt][ks][1], ah[mt][ks][2], ah[mt][ks][3],
                         bl[2 * ks], bl[2 * ks + 1]);
                mma_bf16(d[0], d[1], d[2], d[3],
                         al[mt][ks][0], al[mt][ks][1], al[mt][ks][2], al[mt][ks][3],
                         bh[2 * ks], bh[2 * ks + 1]);
            }
        }
        // store: D[g][2t],D[g][2t+1] and D[g+8][2t],D[g+8][2t+1] per mtile
        #pragma unroll
        for (int mt = 0; mt < 2; mt++) {
            const int m0 = 32 * wid + 16 * mt + g;
            float* op = out + (size_t)h * kL + 8 * jt + 2 * t;
            float2 v0, v1;
            v0.x = dA[mt][0] + dB[mt][0];
            v0.y = dA[mt][1] + dB[mt][1];
            v1.x = dA[mt][2] + dB[mt][2];
            v1.y = dA[mt][3] + dB[mt][3];
            *(float2*)(op + 32 * m0)       = v0;
            *(float2*)(op + 32 * (m0 + 8)) = v1;
        }
    }
}

extern "C" void kernel_launch(void* const* d_in, const int* in_sizes, int n_in,
                              void* d_out, int out_size) {
    const float* log_dt     = (const float*)d_in[0];
    const float* C_real     = (const float*)d_in[1];
    const float* C_imag     = (const float*)d_in[2];
    const float* log_A_real = (const float*)d_in[3];
    const float* A_imag     = (const float*)d_in[4];
    float* out = (float*)d_out;

    s4d_kernel<<<kH, kTPB>>>(log_dt, C_real, C_imag, log_A_real, A_imag, out);
}